// round 1
// baseline (speedup 1.0000x reference)
#include <cuda_runtime.h>
#include <math.h>

#define D_MODEL 1024
#define D_STATE 128
#define SEQ_LEN 4096
#define BATCH   4
#define ROWS    (BATCH * SEQ_LEN)   // 16384
#define LN_EPS  1e-3f

// ---------------- scratch (allocation-free: __device__ globals) ----------------
__device__ float g_xn [ROWS * D_MODEL];   // 64 MB
__device__ float g_z  [ROWS * D_MODEL];   // 64 MB
__device__ float g_xs [ROWS * D_STATE];   // 8 MB
__device__ float g_B  [ROWS * D_STATE];   // 8 MB
__device__ float g_C  [ROWS * D_STATE];   // 8 MB
__device__ float g_ysc[ROWS * D_STATE];   // 8 MB
__device__ float g_y1 [ROWS * D_MODEL];   // 64 MB

// ---------------- LayerNorm: one block per row of 1024 ----------------
__global__ __launch_bounds__(256) void ln_kernel(
    const float* __restrict__ x, const float* __restrict__ gamma,
    const float* __restrict__ beta, float* __restrict__ out)
{
    int row = blockIdx.x;
    int tid = threadIdx.x;                       // 256 threads, 4 floats each
    const float4* xr = (const float4*)(x + (size_t)row * D_MODEL);
    float4 v = xr[tid];

    float s  = v.x + v.y + v.z + v.w;
    float sq = v.x*v.x + v.y*v.y + v.z*v.z + v.w*v.w;

    // warp reduce
    #pragma unroll
    for (int o = 16; o > 0; o >>= 1) {
        s  += __shfl_xor_sync(0xffffffffu, s,  o);
        sq += __shfl_xor_sync(0xffffffffu, sq, o);
    }
    __shared__ float sh_s[8], sh_q[8];
    int wid = tid >> 5, lid = tid & 31;
    if (lid == 0) { sh_s[wid] = s; sh_q[wid] = sq; }
    __syncthreads();
    if (wid == 0) {
        float a = (lid < 8) ? sh_s[lid] : 0.f;
        float b = (lid < 8) ? sh_q[lid] : 0.f;
        #pragma unroll
        for (int o = 4; o > 0; o >>= 1) {
            a += __shfl_xor_sync(0xffffffffu, a, o);
            b += __shfl_xor_sync(0xffffffffu, b, o);
        }
        if (lid == 0) { sh_s[0] = a; sh_q[0] = b; }
    }
    __syncthreads();
    float mu   = sh_s[0] * (1.0f / D_MODEL);
    float var  = sh_q[0] * (1.0f / D_MODEL) - mu * mu;
    float rstd = rsqrtf(var + LN_EPS);

    float4 gv = ((const float4*)gamma)[tid];
    float4 bv = ((const float4*)beta)[tid];
    float4 o4;
    o4.x = (v.x - mu) * rstd * gv.x + bv.x;
    o4.y = (v.y - mu) * rstd * gv.y + bv.y;
    o4.z = (v.z - mu) * rstd * gv.z + bv.z;
    o4.w = (v.w - mu) * rstd * gv.w + bv.w;
    ((float4*)(out + (size_t)row * D_MODEL))[tid] = o4;
}

// ---------------- SGEMM: C = A[MxK] * B[KxN] (+ epilogues) ----------------
// 128x128 blocktile, BK=8, 256 threads, 8x8 per-thread microtile.
template<bool HAS_BIAS, bool HAS_DAUX, bool HAS_RES>
__global__ __launch_bounds__(256) void sgemm_k(
    const float* __restrict__ A, const float* __restrict__ B, float* __restrict__ C,
    int M, int N, int K,
    const float* __restrict__ bias,
    const float* __restrict__ dvec, const float* __restrict__ aux,
    const float* __restrict__ res)
{
    constexpr int BM = 128, BN = 128, BK = 8, TM = 8, TN = 8;
    __shared__ float As[BK][BM];
    __shared__ float Bs[BK][BN];

    int tid = threadIdx.x;
    // load indices
    int a_row = tid >> 1;            // 0..127
    int a_col = (tid & 1) * 4;       // 0 or 4
    int b_row = tid >> 5;            // 0..7
    int b_col = (tid & 31) * 4;      // 0..124
    // compute indices
    int tr = tid >> 4;               // 0..15
    int tc = tid & 15;               // 0..15

    const float* Ab = A + (size_t)blockIdx.y * BM * K;
    const float* Bb = B + (size_t)blockIdx.x * BN;

    float acc[TM][TN];
    #pragma unroll
    for (int i = 0; i < TM; i++)
        #pragma unroll
        for (int j = 0; j < TN; j++) acc[i][j] = 0.f;

    float rA[TM], rB[TN];

    for (int k0 = 0; k0 < K; k0 += BK) {
        float4 av = *(const float4*)(Ab + (size_t)a_row * K + k0 + a_col);
        As[a_col + 0][a_row] = av.x;
        As[a_col + 1][a_row] = av.y;
        As[a_col + 2][a_row] = av.z;
        As[a_col + 3][a_row] = av.w;
        float4 bv = *(const float4*)(Bb + (size_t)(k0 + b_row) * N + b_col);
        *(float4*)&Bs[b_row][b_col] = bv;
        __syncthreads();

        #pragma unroll
        for (int kk = 0; kk < BK; kk++) {
            #pragma unroll
            for (int i = 0; i < TM; i++) rA[i] = As[kk][tr * TM + i];
            #pragma unroll
            for (int j = 0; j < TN; j++) rB[j] = Bs[kk][tc * TN + j];
            #pragma unroll
            for (int i = 0; i < TM; i++)
                #pragma unroll
                for (int j = 0; j < TN; j++)
                    acc[i][j] = fmaf(rA[i], rB[j], acc[i][j]);
        }
        __syncthreads();
    }

    int row0 = blockIdx.y * BM + tr * TM;
    int col0 = blockIdx.x * BN + tc * TN;
    #pragma unroll
    for (int i = 0; i < TM; i++) {
        size_t off = (size_t)(row0 + i) * N + col0;
        #pragma unroll
        for (int jj = 0; jj < TN; jj += 4) {
            float4 v = make_float4(acc[i][jj], acc[i][jj+1], acc[i][jj+2], acc[i][jj+3]);
            if (HAS_BIAS) {
                float4 b4 = *(const float4*)(bias + col0 + jj);
                v.x += b4.x; v.y += b4.y; v.z += b4.z; v.w += b4.w;
            }
            if (HAS_DAUX) {
                float4 d4 = *(const float4*)(dvec + col0 + jj);
                float4 a4 = *(const float4*)(aux + off + jj);
                v.x += d4.x * a4.x; v.y += d4.y * a4.y;
                v.z += d4.z * a4.z; v.w += d4.w * a4.w;
            }
            if (HAS_RES) {
                float4 r4 = *(const float4*)(res + off + jj);
                v.x += r4.x; v.y += r4.y; v.z += r4.z; v.w += r4.w;
            }
            *(float4*)(C + off + jj) = v;
        }
    }
}

// ---------------- Scan: y[t] = lam*y[t-1] + xs[t]*B[t]; out = y*C ----------------
// Exactly reproduces the FFT causal convolution with K[t]=exp(A*t), K[0]=1.
// grid = BATCH blocks, D_STATE threads; loads along t are fully coalesced
// (state is the contiguous dim).
__global__ __launch_bounds__(128) void scan_kernel(
    const float* __restrict__ xs, const float* __restrict__ Bsel,
    const float* __restrict__ Csel, const float* __restrict__ A_log,
    float* __restrict__ out)
{
    int b = blockIdx.x;
    int s = threadIdx.x;
    float lam = expf(-expf(A_log[s]));
    size_t base = (size_t)b * SEQ_LEN * D_STATE + s;
    float y = 0.f;
    #pragma unroll 8
    for (int t = 0; t < SEQ_LEN; t++) {
        size_t i = base + (size_t)t * D_STATE;
        float u = xs[i] * Bsel[i];
        y = fmaf(lam, y, u);
        out[i] = y * Csel[i];
    }
}

// ---------------- launch ----------------
extern "C" void kernel_launch(void* const* d_in, const int* in_sizes, int n_in,
                              void* d_out, int out_size)
{
    const float* x        = (const float*)d_in[0];
    const float* ln_gamma = (const float*)d_in[1];
    const float* ln_beta  = (const float*)d_in[2];
    const float* W_in     = (const float*)d_in[3];
    const float* b_in     = (const float*)d_in[4];
    const float* W_xs     = (const float*)d_in[5];
    const float* W_B      = (const float*)d_in[6];
    const float* b_B      = (const float*)d_in[7];
    const float* W_C      = (const float*)d_in[8];
    const float* b_C      = (const float*)d_in[9];
    const float* A_log    = (const float*)d_in[10];
    const float* Dv       = (const float*)d_in[11];
    const float* W_so     = (const float*)d_in[12];
    const float* W_out    = (const float*)d_in[13];
    const float* b_out    = (const float*)d_in[14];
    float* out = (float*)d_out;

    float *p_xn, *p_z, *p_xs, *p_B, *p_C, *p_ysc, *p_y1;
    cudaGetSymbolAddress((void**)&p_xn,  g_xn);
    cudaGetSymbolAddress((void**)&p_z,   g_z);
    cudaGetSymbolAddress((void**)&p_xs,  g_xs);
    cudaGetSymbolAddress((void**)&p_B,   g_B);
    cudaGetSymbolAddress((void**)&p_C,   g_C);
    cudaGetSymbolAddress((void**)&p_ysc, g_ysc);
    cudaGetSymbolAddress((void**)&p_y1,  g_y1);

    // 1. LayerNorm
    ln_kernel<<<ROWS, 256>>>(x, ln_gamma, ln_beta, p_xn);

    // 2. z = xn @ W_in + b_in     [16384 x 1024] * [1024 x 1024]
    sgemm_k<true, false, false><<<dim3(D_MODEL/128, ROWS/128), 256>>>(
        p_xn, W_in, p_z, ROWS, D_MODEL, D_MODEL, b_in, nullptr, nullptr, nullptr);

    // 3-5. state projections: [16384 x 128] each, K = 1024
    sgemm_k<false, false, false><<<dim3(1, ROWS/128), 256>>>(
        p_z, W_xs, p_xs, ROWS, D_STATE, D_MODEL, nullptr, nullptr, nullptr, nullptr);
    sgemm_k<true, false, false><<<dim3(1, ROWS/128), 256>>>(
        p_z, W_B, p_B, ROWS, D_STATE, D_MODEL, b_B, nullptr, nullptr, nullptr);
    sgemm_k<true, false, false><<<dim3(1, ROWS/128), 256>>>(
        p_z, W_C, p_C, ROWS, D_STATE, D_MODEL, b_C, nullptr, nullptr, nullptr);

    // 6. linear recurrence (== FFT causal conv), fused u = xs*B and *C epilogue
    scan_kernel<<<BATCH, D_STATE>>>(p_xs, p_B, p_C, A_log, p_ysc);

    // 7. y1 = ysc @ W_so + D*z     [16384 x 1024], K = 128
    sgemm_k<false, true, false><<<dim3(D_MODEL/128, ROWS/128), 256>>>(
        p_ysc, W_so, p_y1, ROWS, D_MODEL, D_STATE, nullptr, Dv, p_z, nullptr);

    // 8. out = y1 @ W_out + b_out + x     [16384 x 1024], K = 1024
    sgemm_k<true, false, true><<<dim3(D_MODEL/128, ROWS/128), 256>>>(
        p_y1, W_out, out, ROWS, D_MODEL, D_MODEL, b_out, nullptr, nullptr, x);
}

// round 3
// speedup vs baseline: 2.2181x; 2.2181x over previous
#include <cuda_runtime.h>
#include <cuda_bf16.h>
#include <math.h>
#include <stdint.h>

#define D_MODEL 1024
#define D_STATE 128
#define SEQ_LEN 4096
#define BATCH   4
#define ROWS    (BATCH * SEQ_LEN)        // 16384
#define LN_EPS  1e-3f
#define KEFF_BIG (3 * D_MODEL)           // 3072
#define KEFF_SML (3 * D_STATE)           // 384
#define NPROJ    (3 * D_STATE)           // 384 (xs|B|C packed)

// ---------------- scratch (allocation-free: __device__ globals) ----------------
__device__ __nv_bfloat16 g_xn_sp [(size_t)ROWS * KEFF_BIG];
__device__ float         g_z     [(size_t)ROWS * D_MODEL];
__device__ __nv_bfloat16 g_z_sp  [(size_t)ROWS * KEFF_BIG];
__device__ float         g_proj  [(size_t)ROWS * NPROJ];
__device__ __nv_bfloat16 g_ysc_sp[(size_t)ROWS * KEFF_SML];
__device__ __nv_bfloat16 g_y1_sp [(size_t)ROWS * KEFF_BIG];
__device__ __nv_bfloat16 g_Win_p [(size_t)D_MODEL * KEFF_BIG];
__device__ __nv_bfloat16 g_Wpk_p [(size_t)NPROJ   * KEFF_BIG];
__device__ __nv_bfloat16 g_Wso_p [(size_t)D_MODEL * KEFF_SML];
__device__ __nv_bfloat16 g_Wout_p[(size_t)D_MODEL * KEFF_BIG];
__device__ float g_bpk[NPROJ];
__device__ float g_carry[BATCH * 64 * D_STATE];

// ---------------- helpers ----------------
__device__ __forceinline__ uint32_t cvta_smem(const void* p) {
    uint32_t a;
    asm("{ .reg .u64 t; cvta.to.shared.u64 t, %1; cvt.u32.u64 %0, t; }" : "=r"(a) : "l"(p));
    return a;
}
__device__ __forceinline__ uint32_t pack_bf2(__nv_bfloat16 a, __nv_bfloat16 b) {
    __nv_bfloat162 t; t.x = a; t.y = b;
    return *reinterpret_cast<uint32_t*>(&t);
}

// ---------------- LayerNorm -> split bf16 [hi | lo | hi] ----------------
__global__ __launch_bounds__(256) void ln_split_kernel(
    const float* __restrict__ x, const float* __restrict__ gamma,
    const float* __restrict__ beta, __nv_bfloat16* __restrict__ outp)
{
    int row = blockIdx.x;
    int tid = threadIdx.x;
    const float4* xr = (const float4*)(x + (size_t)row * D_MODEL);
    float4 v = xr[tid];

    float s  = v.x + v.y + v.z + v.w;
    float sq = v.x*v.x + v.y*v.y + v.z*v.z + v.w*v.w;
    #pragma unroll
    for (int o = 16; o > 0; o >>= 1) {
        s  += __shfl_xor_sync(0xffffffffu, s,  o);
        sq += __shfl_xor_sync(0xffffffffu, sq, o);
    }
    __shared__ float sh_s[8], sh_q[8];
    int wid = tid >> 5, lid = tid & 31;
    if (lid == 0) { sh_s[wid] = s; sh_q[wid] = sq; }
    __syncthreads();
    if (wid == 0) {
        float a = (lid < 8) ? sh_s[lid] : 0.f;
        float b = (lid < 8) ? sh_q[lid] : 0.f;
        #pragma unroll
        for (int o = 4; o > 0; o >>= 1) {
            a += __shfl_xor_sync(0xffffffffu, a, o);
            b += __shfl_xor_sync(0xffffffffu, b, o);
        }
        if (lid == 0) { sh_s[0] = a; sh_q[0] = b; }
    }
    __syncthreads();
    float mu   = sh_s[0] * (1.0f / D_MODEL);
    float var  = sh_q[0] * (1.0f / D_MODEL) - mu * mu;
    float rstd = rsqrtf(var + LN_EPS);

    float4 gv = ((const float4*)gamma)[tid];
    float4 bv = ((const float4*)beta)[tid];
    float o0 = (v.x - mu) * rstd * gv.x + bv.x;
    float o1 = (v.y - mu) * rstd * gv.y + bv.y;
    float o2 = (v.z - mu) * rstd * gv.z + bv.z;
    float o3 = (v.w - mu) * rstd * gv.w + bv.w;

    __nv_bfloat16 h0 = __float2bfloat16(o0), h1 = __float2bfloat16(o1);
    __nv_bfloat16 h2 = __float2bfloat16(o2), h3 = __float2bfloat16(o3);
    __nv_bfloat16 l0 = __float2bfloat16(o0 - __bfloat162float(h0));
    __nv_bfloat16 l1 = __float2bfloat16(o1 - __bfloat162float(h1));
    __nv_bfloat16 l2 = __float2bfloat16(o2 - __bfloat162float(h2));
    __nv_bfloat16 l3 = __float2bfloat16(o3 - __bfloat162float(h3));

    uint2 hv = make_uint2(pack_bf2(h0, h1), pack_bf2(h2, h3));
    uint2 lv = make_uint2(pack_bf2(l0, l1), pack_bf2(l2, l3));
    __nv_bfloat16* base = outp + (size_t)row * KEFF_BIG + tid * 4;
    *(uint2*)(base)                 = hv;
    *(uint2*)(base + D_MODEL)       = lv;
    *(uint2*)(base + 2 * D_MODEL)   = hv;
}

// ---------------- weight prep: W[K,N] fp32 -> Wp[N, 3K] bf16 [hi | hi | lo] ----------------
__global__ void prep_weight(const float* __restrict__ W, __nv_bfloat16* __restrict__ Wp,
                            int K, int N)
{
    int idx = blockIdx.x * blockDim.x + threadIdx.x;
    if (idx >= K * N) return;
    int k = idx / N, n = idx % N;
    float w = W[idx];
    __nv_bfloat16 hi = __float2bfloat16(w);
    __nv_bfloat16 lo = __float2bfloat16(w - __bfloat162float(hi));
    size_t base = (size_t)n * 3 * K;
    Wp[base + k]         = hi;
    Wp[base + K + k]     = hi;
    Wp[base + 2 * K + k] = lo;
}

__global__ void prep_bias(const float* __restrict__ bB, const float* __restrict__ bC,
                          float* __restrict__ bp)
{
    int i = threadIdx.x;
    bp[i] = (i < 128) ? 0.f : ((i < 256) ? bB[i - 128] : bC[i - 256]);
}

// ---------------- HMMA GEMM: C[M, Nc] = A'[M,Keff] @ B'[Nc,Keff]^T ----------------
// 128x128 CTA tile, 8 warps (2 M x 4 N), warp tile 64x32, BK=32, 4-stage cp.async.
#define BM 128
#define BN 128
#define BK 32
#define NSTAGE 4
#define RS 40                                  // smem row stride in bf16 (80 bytes)
#define A_TILE_BYTES (BM * RS * 2)             // 10240
#define STAGE_BYTES  (2 * BM * RS * 2)         // 20480 (A + B)
#define GEMM_SMEM    (NSTAGE * STAGE_BYTES)    // 81920

#define MMA_BF16(d, a, b) \
    asm volatile( \
        "mma.sync.aligned.m16n8k16.row.col.f32.bf16.bf16.f32 " \
        "{%0,%1,%2,%3}, {%4,%5,%6,%7}, {%8,%9}, {%0,%1,%2,%3};" \
        : "+f"((d)[0]), "+f"((d)[1]), "+f"((d)[2]), "+f"((d)[3]) \
        : "r"((a)[0]), "r"((a)[1]), "r"((a)[2]), "r"((a)[3]), \
          "r"((b)[0]), "r"((b)[1]))

#define LDSM_X4(r, addr) \
    asm volatile("ldmatrix.sync.aligned.m8n8.x4.shared.b16 {%0,%1,%2,%3}, [%4];" \
        : "=r"((r)[0]), "=r"((r)[1]), "=r"((r)[2]), "=r"((r)[3]) : "r"(addr))

template<bool HAS_BIAS, bool HAS_DAUX, bool HAS_RES, bool WF32, bool WSPLIT>
__global__ __launch_bounds__(256)
void gemm_tc(const __nv_bfloat16* __restrict__ A, const __nv_bfloat16* __restrict__ Bw,
             int Keff, int Nc,
             float* __restrict__ Cf, __nv_bfloat16* __restrict__ Csp,
             const float* __restrict__ bias, const float* __restrict__ dvec,
             const float* __restrict__ aux, const float* __restrict__ res)
{
    extern __shared__ __align__(128) char smem[];
    const int tid  = threadIdx.x;
    const int warp = tid >> 5, lane = tid & 31;
    const int wm = warp & 1, wn = warp >> 1;     // 2 x 4 warp grid
    const int m0 = blockIdx.y * BM, n0 = blockIdx.x * BN;
    const uint32_t smem_base = cvta_smem(smem);

    const int NK = Keff / BK;
    const __nv_bfloat16* Ab = A  + (size_t)m0 * Keff;
    const __nv_bfloat16* Bb = Bw + (size_t)n0 * Keff;
    const size_t row_bytes = (size_t)Keff * 2;

    float acc[4][4][4];
    #pragma unroll
    for (int i = 0; i < 4; i++)
        #pragma unroll
        for (int j = 0; j < 4; j++)
            #pragma unroll
            for (int e = 0; e < 4; e++) acc[i][j][e] = 0.f;

    // stage loader: 256 threads, A: 128 rows x 64B (4 chunks), B same.
    auto load_stage = [&](int sk, int buf) {
        const uint32_t sb = smem_base + buf * STAGE_BYTES;
        const size_t kbyte = (size_t)sk * BK * 2;       // 64 B per stage step
        #pragma unroll
        for (int j = 0; j < 2; j++) {
            int chunk = tid + j * 256;                  // 0..511
            int row = chunk >> 2, cb = chunk & 3;
            const char* ga = (const char*)Ab + (size_t)row * row_bytes + kbyte + cb * 16;
            uint32_t da = sb + row * 80 + cb * 16;
            asm volatile("cp.async.cg.shared.global [%0], [%1], 16;" :: "r"(da), "l"(ga));
        }
        #pragma unroll
        for (int j = 0; j < 2; j++) {
            int chunk = tid + j * 256;
            int row = chunk >> 2, cb = chunk & 3;
            const char* gb = (const char*)Bb + (size_t)row * row_bytes + kbyte + cb * 16;
            uint32_t db = sb + A_TILE_BYTES + row * 80 + cb * 16;
            asm volatile("cp.async.cg.shared.global [%0], [%1], 16;" :: "r"(db), "l"(gb));
        }
        asm volatile("cp.async.commit_group;");
    };

    #pragma unroll
    for (int s = 0; s < NSTAGE - 1; s++) load_stage(s, s);

    // lane-invariant ldmatrix address pieces: row = (lane & 15), k-half = (lane >> 4)
    const uint32_t lrow = (lane & 15);
    const uint32_t lkb  = (lane >> 4) * 16;             // bytes

    for (int i = 0; i < NK; i++) {
        asm volatile("cp.async.wait_group 2;");
        __syncthreads();

        int nxt = i + NSTAGE - 1;
        if (nxt < NK) load_stage(nxt, nxt & (NSTAGE - 1));
        else          asm volatile("cp.async.commit_group;");

        const uint32_t sb = smem_base + (i & (NSTAGE - 1)) * STAGE_BYTES;
        const uint32_t abase = sb + (wm * 64) * 80;
        const uint32_t bbase = sb + A_TILE_BYTES + (wn * 32) * 80;

        #pragma unroll
        for (int ks = 0; ks < 2; ks++) {
            uint32_t Af[4][4], Bf[2][4];
            #pragma unroll
            for (int mt = 0; mt < 4; mt++)
                LDSM_X4(Af[mt], abase + (mt * 16 + lrow) * 80 + ks * 32 + lkb);
            #pragma unroll
            for (int g = 0; g < 2; g++)
                LDSM_X4(Bf[g], bbase + (g * 16 + lrow) * 80 + ks * 32 + lkb);

            #pragma unroll
            for (int mt = 0; mt < 4; mt++) {
                #pragma unroll
                for (int nt = 0; nt < 4; nt++) {
                    uint32_t b2[2] = { Bf[nt >> 1][nt & 1], Bf[nt >> 1][(nt & 1) + 2] };
                    MMA_BF16(acc[mt][nt], Af[mt], b2);
                }
            }
        }
    }
    __syncthreads();   // all compute done before smem reuse

    // ---- acc -> smem bounce ----
    float* stile = (float*)smem;               // [128][132]
    const int groupID = lane >> 2, tig = lane & 3;
    #pragma unroll
    for (int mt = 0; mt < 4; mt++) {
        int r0 = wm * 64 + mt * 16 + groupID;
        #pragma unroll
        for (int nt = 0; nt < 4; nt++) {
            int c = wn * 32 + nt * 8 + tig * 2;
            *(float2*)&stile[r0 * 132 + c]       = make_float2(acc[mt][nt][0], acc[mt][nt][1]);
            *(float2*)&stile[(r0 + 8) * 132 + c] = make_float2(acc[mt][nt][2], acc[mt][nt][3]);
        }
    }
    __syncthreads();

    // ---- fused coalesced epilogue: warp w covers rows w*16 .. w*16+15 ----
    float4 b4 = make_float4(0.f, 0.f, 0.f, 0.f), d4 = b4;
    int col = n0 + lane * 4;
    if (HAS_BIAS) b4 = *(const float4*)(bias + col);
    if (HAS_DAUX) d4 = *(const float4*)(dvec + col);

    #pragma unroll 4
    for (int rr = 0; rr < 16; rr++) {
        int r = warp * 16 + rr;
        int row = m0 + r;
        float4 v = *(float4*)&stile[r * 132 + lane * 4];
        if (HAS_BIAS) { v.x += b4.x; v.y += b4.y; v.z += b4.z; v.w += b4.w; }
        if (HAS_DAUX) {
            float4 a4 = *(const float4*)(aux + (size_t)row * Nc + col);
            v.x += d4.x * a4.x; v.y += d4.y * a4.y; v.z += d4.z * a4.z; v.w += d4.w * a4.w;
        }
        if (HAS_RES) {
            float4 r4 = *(const float4*)(res + (size_t)row * Nc + col);
            v.x += r4.x; v.y += r4.y; v.z += r4.z; v.w += r4.w;
        }
        if (WF32) *(float4*)(Cf + (size_t)row * Nc + col) = v;
        if (WSPLIT) {
            __nv_bfloat16 h0 = __float2bfloat16(v.x), h1 = __float2bfloat16(v.y);
            __nv_bfloat16 h2 = __float2bfloat16(v.z), h3 = __float2bfloat16(v.w);
            __nv_bfloat16 l0 = __float2bfloat16(v.x - __bfloat162float(h0));
            __nv_bfloat16 l1 = __float2bfloat16(v.y - __bfloat162float(h1));
            __nv_bfloat16 l2 = __float2bfloat16(v.z - __bfloat162float(h2));
            __nv_bfloat16 l3 = __float2bfloat16(v.w - __bfloat162float(h3));
            uint2 hv = make_uint2(pack_bf2(h0, h1), pack_bf2(h2, h3));
            uint2 lv = make_uint2(pack_bf2(l0, l1), pack_bf2(l2, l3));
            __nv_bfloat16* bp = Csp + (size_t)row * 3 * Nc + col;
            *(uint2*)(bp)          = hv;
            *(uint2*)(bp + Nc)     = lv;
            *(uint2*)(bp + 2 * Nc) = hv;
        }
    }
}

// ---------------- chunked scan (== FFT causal conv) ----------------
#define CHUNK 64
#define NCHUNK (SEQ_LEN / CHUNK)

__global__ __launch_bounds__(128) void scan1(const float* __restrict__ proj,
                                             const float* __restrict__ A_log,
                                             float* __restrict__ carry)
{
    int c = blockIdx.x, b = blockIdx.y, s = threadIdx.x;
    float lam = expf(-expf(A_log[s]));
    size_t row0 = (size_t)b * SEQ_LEN + c * CHUNK;
    float y = 0.f;
    #pragma unroll 8
    for (int t = 0; t < CHUNK; t++) {
        const float* p = proj + (row0 + t) * NPROJ;
        y = fmaf(lam, y, p[s] * p[128 + s]);
    }
    carry[(b * NCHUNK + c) * D_STATE + s] = y;
}

__global__ __launch_bounds__(128) void scan2(const float* __restrict__ A_log,
                                             float* __restrict__ carry)
{
    int b = blockIdx.x, s = threadIdx.x;
    float lam64 = expf(-expf(A_log[s]) * (float)CHUNK);
    float S = 0.f;
    for (int c = 0; c < NCHUNK; c++) {
        size_t i = (size_t)(b * NCHUNK + c) * D_STATE + s;
        float f = carry[i];
        carry[i] = S;
        S = fmaf(lam64, S, f);
    }
}

__global__ __launch_bounds__(128) void scan3(const float* __restrict__ proj,
                                             const float* __restrict__ A_log,
                                             const float* __restrict__ carry,
                                             __nv_bfloat16* __restrict__ ysp)
{
    int c = blockIdx.x, b = blockIdx.y, s = threadIdx.x;
    float lam = expf(-expf(A_log[s]));
    float y = carry[(b * NCHUNK + c) * D_STATE + s];
    size_t row0 = (size_t)b * SEQ_LEN + c * CHUNK;
    #pragma unroll 4
    for (int t = 0; t < CHUNK; t++) {
        size_t row = row0 + t;
        const float* p = proj + row * NPROJ;
        y = fmaf(lam, y, p[s] * p[128 + s]);
        float o = y * p[256 + s];
        __nv_bfloat16 hi = __float2bfloat16(o);
        __nv_bfloat16 lo = __float2bfloat16(o - __bfloat162float(hi));
        __nv_bfloat16* bp = ysp + row * KEFF_SML;
        bp[s]                 = hi;
        bp[D_STATE + s]       = lo;
        bp[2 * D_STATE + s]   = hi;
    }
}

// ---------------- launch ----------------
extern "C" void kernel_launch(void* const* d_in, const int* in_sizes, int n_in,
                              void* d_out, int out_size)
{
    const float* x        = (const float*)d_in[0];
    const float* ln_gamma = (const float*)d_in[1];
    const float* ln_beta  = (const float*)d_in[2];
    const float* W_in     = (const float*)d_in[3];
    const float* b_in     = (const float*)d_in[4];
    const float* W_xs     = (const float*)d_in[5];
    const float* W_B      = (const float*)d_in[6];
    const float* b_B      = (const float*)d_in[7];
    const float* W_C      = (const float*)d_in[8];
    const float* b_C      = (const float*)d_in[9];
    const float* A_log    = (const float*)d_in[10];
    const float* Dv       = (const float*)d_in[11];
    const float* W_so     = (const float*)d_in[12];
    const float* W_out    = (const float*)d_in[13];
    const float* b_out    = (const float*)d_in[14];
    float* out = (float*)d_out;

    __nv_bfloat16 *p_xn_sp, *p_z_sp, *p_ysc_sp, *p_y1_sp;
    __nv_bfloat16 *p_Win, *p_Wpk, *p_Wso, *p_Wout;
    float *p_z, *p_proj, *p_bpk, *p_carry;
    cudaGetSymbolAddress((void**)&p_xn_sp,  g_xn_sp);
    cudaGetSymbolAddress((void**)&p_z,      g_z);
    cudaGetSymbolAddress((void**)&p_z_sp,   g_z_sp);
    cudaGetSymbolAddress((void**)&p_proj,   g_proj);
    cudaGetSymbolAddress((void**)&p_ysc_sp, g_ysc_sp);
    cudaGetSymbolAddress((void**)&p_y1_sp,  g_y1_sp);
    cudaGetSymbolAddress((void**)&p_Win,    g_Win_p);
    cudaGetSymbolAddress((void**)&p_Wpk,    g_Wpk_p);
    cudaGetSymbolAddress((void**)&p_Wso,    g_Wso_p);
    cudaGetSymbolAddress((void**)&p_Wout,   g_Wout_p);
    cudaGetSymbolAddress((void**)&p_bpk,    g_bpk);
    cudaGetSymbolAddress((void**)&p_carry,  g_carry);

    cudaFuncSetAttribute(gemm_tc<true,  false, false, true,  true >, cudaFuncAttributeMaxDynamicSharedMemorySize, GEMM_SMEM);
    cudaFuncSetAttribute(gemm_tc<true,  false, false, true,  false>, cudaFuncAttributeMaxDynamicSharedMemorySize, GEMM_SMEM);
    cudaFuncSetAttribute(gemm_tc<false, true,  false, false, true >, cudaFuncAttributeMaxDynamicSharedMemorySize, GEMM_SMEM);
    cudaFuncSetAttribute(gemm_tc<true,  false, true,  true,  false>, cudaFuncAttributeMaxDynamicSharedMemorySize, GEMM_SMEM);

    // ---- weight prep ----
    prep_weight<<<(D_MODEL * D_MODEL + 255) / 256, 256>>>(W_in,  p_Win,  D_MODEL, D_MODEL);
    prep_weight<<<(D_MODEL * D_STATE + 255) / 256, 256>>>(W_xs,  p_Wpk,                          D_MODEL, D_STATE);
    prep_weight<<<(D_MODEL * D_STATE + 255) / 256, 256>>>(W_B,   p_Wpk + (size_t)128 * KEFF_BIG, D_MODEL, D_STATE);
    prep_weight<<<(D_MODEL * D_STATE + 255) / 256, 256>>>(W_C,   p_Wpk + (size_t)256 * KEFF_BIG, D_MODEL, D_STATE);
    prep_weight<<<(D_STATE * D_MODEL + 255) / 256, 256>>>(W_so,  p_Wso,  D_STATE, D_MODEL);
    prep_weight<<<(D_MODEL * D_MODEL + 255) / 256, 256>>>(W_out, p_Wout, D_MODEL, D_MODEL);
    prep_bias<<<1, NPROJ>>>(b_B, b_C, p_bpk);

    // ---- 1. LayerNorm -> split bf16 ----
    ln_split_kernel<<<ROWS, 256>>>(x, ln_gamma, ln_beta, p_xn_sp);

    // ---- 2. z = xn @ W_in + b_in (fp32 z + split z') ----
    gemm_tc<true, false, false, true, true><<<dim3(D_MODEL / BN, ROWS / BM), 256, GEMM_SMEM>>>(
        p_xn_sp, p_Win, KEFF_BIG, D_MODEL, p_z, p_z_sp, b_in, nullptr, nullptr, nullptr);

    // ---- 3. packed projections: [xs | B | C] ----
    gemm_tc<true, false, false, true, false><<<dim3(NPROJ / BN, ROWS / BM), 256, GEMM_SMEM>>>(
        p_z_sp, p_Wpk, KEFF_BIG, NPROJ, p_proj, nullptr, p_bpk, nullptr, nullptr, nullptr);

    // ---- 4. chunked linear recurrence (== FFT causal conv) ----
    scan1<<<dim3(NCHUNK, BATCH), 128>>>(p_proj, A_log, p_carry);
    scan2<<<BATCH, 128>>>(A_log, p_carry);
    scan3<<<dim3(NCHUNK, BATCH), 128>>>(p_proj, A_log, p_carry, p_ysc_sp);

    // ---- 5. y1 = ysc @ W_so + D*z (split only) ----
    gemm_tc<false, true, false, false, true><<<dim3(D_MODEL / BN, ROWS / BM), 256, GEMM_SMEM>>>(
        p_ysc_sp, p_Wso, KEFF_SML, D_MODEL, nullptr, p_y1_sp, nullptr, Dv, p_z, nullptr);

    // ---- 6. out = y1 @ W_out + b_out + x ----
    gemm_tc<true, false, true, true, false><<<dim3(D_MODEL / BN, ROWS / BM), 256, GEMM_SMEM>>>(
        p_y1_sp, p_Wout, KEFF_BIG, D_MODEL, out, nullptr, b_out, nullptr, nullptr, x);
}